// round 15
// baseline (speedup 1.0000x reference)
#include <cuda_runtime.h>
#include <cuda_fp16.h>
#include <cstdint>
#include <cstddef>

// ---------------- problem constants ----------------
#define BATCH 256
#define C1 256
#define H1 20
#define KDIM 20736        // 256*81
#define NDIM 9216         // 256*36
#define MDIM 256
#define NPOS 36
#define NCAPS 1152
#define VIN 8
#define NOUT 10
#define VOUT 16

#define A_SCALE 64.0f
#define A_INV_SCALE (1.0f / 64.0f)

// ---------------- scratch (device globals; allocation-free) ----------------
__device__ __half g_h16[(size_t)BATCH * C1 * 400];             // conv1 out fp16
__device__ __half g_Ah[(size_t)MDIM * KDIM];                   // 64*weights fp16
__device__ __half g_Bh[(size_t)NDIM * KDIM];                   // im2col fp16
__device__ float g_c2[(size_t)MDIM * NDIM];
__device__ float g_caps[(size_t)BATCH * NCAPS * VIN];
__device__ __half g_uhat[(size_t)BATCH * NCAPS * NOUT * VOUT]; // fp16 u_hat

// =================== PTX helpers ===================
__device__ __forceinline__ uint32_t smem_u32(const void* p) {
    uint32_t a;
    asm("{ .reg .u64 t; cvta.to.shared.u64 t, %1; cvt.u32.u64 %0, t; }"
        : "=r"(a) : "l"(p));
    return a;
}
__device__ __forceinline__ void cp_async16(uint32_t dst, const void* src) {
    asm volatile("cp.async.cg.shared.global [%0], [%1], 16;" :: "r"(dst), "l"(src));
}
#define CP_COMMIT() asm volatile("cp.async.commit_group;" ::: "memory")
#define CP_WAIT3()  asm volatile("cp.async.wait_group 3;" ::: "memory")

__device__ __forceinline__ void ldsm_x4(uint32_t* r, uint32_t addr) {
    asm volatile("ldmatrix.sync.aligned.m8n8.x4.shared.b16 {%0,%1,%2,%3}, [%4];"
                 : "=r"(r[0]), "=r"(r[1]), "=r"(r[2]), "=r"(r[3]) : "r"(addr));
}
__device__ __forceinline__ void mma_fp16(float* d, const uint32_t* a, const uint32_t* b) {
    asm volatile(
        "mma.sync.aligned.m16n8k16.row.col.f32.f16.f16.f32 "
        "{%0,%1,%2,%3}, {%4,%5,%6,%7}, {%8,%9}, {%0,%1,%2,%3};"
        : "+f"(d[0]), "+f"(d[1]), "+f"(d[2]), "+f"(d[3])
        : "r"(a[0]), "r"(a[1]), "r"(a[2]), "r"(a[3]), "r"(b[0]), "r"(b[1]));
}

// ---------------- conv1 (GEMM-style): [B,1,28,28] -> [B,256,20,20] fp16 out ------
__global__ __launch_bounds__(256) void conv1_kernel(const float* __restrict__ x,
                                                    const float* __restrict__ w,
                                                    const float* __restrict__ bias) {
    __shared__ float img[784];
    __shared__ float ws[81 * 128];
    int b = blockIdx.y;
    int oct = (blockIdx.x / 5) * 128;
    int pt = (blockIdx.x % 5) * 80;
    int tid = threadIdx.x;
    int tx = tid & 15, ty = tid >> 4;

    for (int i = tid; i < 784; i += 256) img[i] = x[(size_t)b * 784 + i];
    for (int idx = tid; idx < 81 * 128; idx += 256) {
        int o = idx / 81, k = idx - o * 81;
        ws[k * 128 + o] = w[(size_t)(oct + o) * 81 + k];
    }
    __syncthreads();

    int ibase[5];
#pragma unroll
    for (int q = 0; q < 5; q++) {
        int pos = pt + q * 16 + tx;
        int py = pos / 20, px = pos - py * 20;
        ibase[q] = py * 28 + px;
    }
    float acc[8][5];
#pragma unroll
    for (int o = 0; o < 8; o++) {
        float bv = bias[oct + ty * 8 + o];
#pragma unroll
        for (int q = 0; q < 5; q++) acc[o][q] = bv;
    }
#pragma unroll
    for (int r = 0; r < 9; r++) {
#pragma unroll
        for (int s = 0; s < 9; s++) {
            int k = r * 9 + s;
            int off = r * 28 + s;
            float iv[5];
#pragma unroll
            for (int q = 0; q < 5; q++) iv[q] = img[ibase[q] + off];
            float4 a0 = *(const float4*)&ws[k * 128 + ty * 8];
            float4 a1 = *(const float4*)&ws[k * 128 + ty * 8 + 4];
            float af[8] = {a0.x, a0.y, a0.z, a0.w, a1.x, a1.y, a1.z, a1.w};
#pragma unroll
            for (int o = 0; o < 8; o++)
#pragma unroll
                for (int q = 0; q < 5; q++) acc[o][q] += af[o] * iv[q];
        }
    }
#pragma unroll
    for (int o = 0; o < 8; o++) {
        int oc = oct + ty * 8 + o;
        __half* dst = g_h16 + ((size_t)b * C1 + oc) * 400 + pt + tx;
#pragma unroll
        for (int q = 0; q < 5; q++) dst[q * 16] = __float2half_rn(acc[o][q]);
    }
}

// ---------------- convert A: (64*pc_w) -> fp16 ----------------
__global__ void convertA_kernel(const float* __restrict__ pc_w) {
    int idx = blockIdx.x * blockDim.x + threadIdx.x;
    if (idx >= MDIM * KDIM) return;
    g_Ah[idx] = __float2half_rn(pc_w[idx] * A_SCALE);
}

// ---------------- im2col: warp-per-row, 16B stores, 1152 blocks x 256 ----------------
__global__ __launch_bounds__(256) void im2colB_kernel() {
    int n = blockIdx.x * 8 + (threadIdx.x >> 5);
    int lane = threadIdx.x & 31;
    int b = n / NPOS;
    int p = n - b * NPOS;
    int py = p / 6, px = p - py * 6;
    const __half* hb = g_h16 + (size_t)b * C1 * 400 + (2 * py) * H1 + 2 * px;
    __half* dst = g_Bh + (size_t)n * KDIM;

    for (int kg = 0; kg < 81; kg++) {
        int k0 = kg * 256 + lane * 8;
        __half h8[8];
#pragma unroll
        for (int e = 0; e < 8; e++) {
            int k = k0 + e;
            int ic = k / 81;
            int rs = k - ic * 81;
            int r = rs / 9, s = rs - r * 9;
            h8[e] = hb[ic * 400 + r * H1 + s];
        }
        *(uint4*)&dst[k0] = *(uint4*)h8;
    }
}

// ---------------- HMMA GEMM: C = A[256,K] * B[9216,K]^T, single fp16 pass --------
// CTA 128x128, K-chunk 64, 5-stage cp.async pipeline (prefetch distance 4),
// 8 warps (2m x 4n), warp tile 64x32. 144 CTAs.
#define GK 64
#define KITERS (KDIM / GK)            // 324
#define PITCH 144
#define A_BYTES (128 * PITCH)         // 18432
#define B_BYTES (128 * PITCH)         // 18432
#define STAGE_BYTES (A_BYTES + B_BYTES)  // 36864
#define NSTAGE 5

__global__ __launch_bounds__(256, 1) void gemm_mma_kernel() {
    extern __shared__ char smem[];
    uint32_t sb = smem_u32(smem);
    int tid = threadIdx.x;
    int wid = tid >> 5, lane = tid & 31;
    int n0 = blockIdx.x * 128;
    int m0 = blockIdx.y * 128;
    int wm = wid >> 2;            // 0..1, m offset 64*wm
    int wn = wid & 3;             // 0..3, n offset 32*wn

    const __half* srcA = g_Ah + (size_t)m0 * KDIM;
    const __half* srcB = g_Bh + (size_t)n0 * KDIM;

    // prologue: issue stages 0..3
#pragma unroll
    for (int st = 0; st < 4; st++) {
        int k0 = st * GK;
        uint32_t dstage = sb + st * STAGE_BYTES;
#pragma unroll
        for (int j = 0; j < 4; j++) {
            int q = tid + j * 256;
            int r = q >> 3, c = q & 7;
            cp_async16(dstage + r * PITCH + c * 16,
                       srcA + (size_t)r * KDIM + k0 + c * 8);
        }
#pragma unroll
        for (int j = 0; j < 4; j++) {
            int q = tid + j * 256;
            int r = q >> 3, c = q & 7;
            cp_async16(dstage + A_BYTES + r * PITCH + c * 16,
                       srcB + (size_t)r * KDIM + k0 + c * 8);
        }
        CP_COMMIT();
    }

    float acc[4][4][4];
#pragma unroll
    for (int i = 0; i < 4; i++)
#pragma unroll
        for (int j = 0; j < 4; j++)
#pragma unroll
            for (int v = 0; v < 4; v++) acc[i][j][v] = 0.f;

    int aRow = wm * 64 + (lane & 15);
    int aColB = (lane >> 4) * 16;
    int bGroup = lane >> 3;
    int bWithin = lane & 7;
    int bRowOff = wn * 32 + ((bGroup >> 1) << 3) + bWithin;
    int bColB = (bGroup & 1) * 16;

    for (int it = 0; it < KITERS; it++) {
        CP_WAIT3();               // <=3 outstanding of 4 -> stage `it` complete
        __syncthreads();
        if (it + 4 < KITERS) {
            int k0 = (it + 4) * GK;
            uint32_t dstage = sb + ((it + 4) % NSTAGE) * STAGE_BYTES;
#pragma unroll
            for (int j = 0; j < 4; j++) {
                int q = tid + j * 256;
                int r = q >> 3, c = q & 7;
                cp_async16(dstage + r * PITCH + c * 16,
                           srcA + (size_t)r * KDIM + k0 + c * 8);
            }
#pragma unroll
            for (int j = 0; j < 4; j++) {
                int q = tid + j * 256;
                int r = q >> 3, c = q & 7;
                cp_async16(dstage + A_BYTES + r * PITCH + c * 16,
                           srcB + (size_t)r * KDIM + k0 + c * 8);
            }
        }
        CP_COMMIT();

        uint32_t stage = sb + (it % NSTAGE) * STAGE_BYTES;
#pragma unroll
        for (int ks = 0; ks < 4; ks++) {
            uint32_t kOffB = ks * 32;
            uint32_t aq[4][4], bq[4][2];
#pragma unroll
            for (int mf = 0; mf < 4; mf++) {
                uint32_t adr = stage + (aRow + mf * 16) * PITCH + aColB + kOffB;
                ldsm_x4(aq[mf], adr);
            }
#pragma unroll
            for (int jp = 0; jp < 2; jp++) {
                uint32_t tmp[4];
                uint32_t adr = stage + A_BYTES +
                               (bRowOff + jp * 16) * PITCH + bColB + kOffB;
                ldsm_x4(tmp, adr);
                bq[jp * 2 + 0][0] = tmp[0]; bq[jp * 2 + 0][1] = tmp[1];
                bq[jp * 2 + 1][0] = tmp[2]; bq[jp * 2 + 1][1] = tmp[3];
            }
#pragma unroll
            for (int mf = 0; mf < 4; mf++)
#pragma unroll
                for (int nf = 0; nf < 4; nf++)
                    mma_fp16(acc[mf][nf], aq[mf], bq[nf]);
        }
    }

    int g = lane >> 2, t = lane & 3;
#pragma unroll
    for (int mf = 0; mf < 4; mf++) {
#pragma unroll
        for (int nf = 0; nf < 4; nf++) {
            int m = m0 + wm * 64 + mf * 16 + g;
            int n = n0 + wn * 32 + nf * 8 + t * 2;
            float* p0 = g_c2 + (size_t)m * NDIM + n;
            float* p1 = g_c2 + (size_t)(m + 8) * NDIM + n;
            *(float2*)p0 = make_float2(acc[mf][nf][0], acc[mf][nf][1]);
            *(float2*)p1 = make_float2(acc[mf][nf][2], acc[mf][nf][3]);
        }
    }
}

// ---------------- bias + un-scale + squash -> caps[B,1152,8] ----------------
__global__ void squash_caps_kernel(const float* __restrict__ pcb) {
    int idx = blockIdx.x * blockDim.x + threadIdx.x;
    if (idx >= BATCH * NCAPS) return;
    int b = idx / NCAPS, i = idx % NCAPS;
    float v[8];
    float mag = 0.f;
#pragma unroll
    for (int k = 0; k < 8; k++) {
        int f = i * 8 + k;
        int oc = f / NPOS, p = f % NPOS;
        float t = g_c2[(size_t)oc * NDIM + b * NPOS + p] * A_INV_SCALE + pcb[oc];
        v[k] = t;
        mag += t * t;
    }
    float scale = mag / ((1.f + mag) * sqrtf(mag));
#pragma unroll
    for (int k = 0; k < 8; k++) g_caps[(size_t)idx * 8 + k] = v[k] * scale;
}

// ---------------- u_hat (fp16 out): grid (1152, 8), block 160 ----------------
__global__ void uhat_kernel(const float* __restrict__ W) {
    int i = blockIdx.x;
    int b0 = blockIdx.y * 32;
    __shared__ float Ws[160 * 8];
    int t = threadIdx.x;
    for (int q = t; q < 1280; q += 160) Ws[q] = W[(size_t)i * 1280 + q];
    __syncthreads();
    float wr[8];
#pragma unroll
    for (int k = 0; k < 8; k++) wr[k] = Ws[t * 8 + k];
    for (int b = b0; b < b0 + 32; b++) {
        const float* cp = g_caps + ((size_t)b * NCAPS + i) * 8;
        float acc = 0.f;
#pragma unroll
        for (int k = 0; k < 8; k++) acc += wr[k] * __ldg(cp + k);
        g_uhat[((size_t)b * NCAPS + i) * 160 + t] = __float2half_rn(acc);
    }
}

// ---------------- fused dynamic routing (u_hat fp16), 1024 threads ----------------
__global__ __launch_bounds__(1024) void routing_kernel(const float* __restrict__ dc_bias,
                                                       float* __restrict__ out) {
    extern __shared__ float sm[];
    float* bs = sm;                  // [1152*10]
    float* swarp = sm + 11520;       // [32*160]
    float* vsm = sm + 11520 + 5120;  // [160]

    int b = blockIdx.x;
    int tid = threadIdx.x;
    int wid = tid >> 5, lane = tid & 31;
    int half = lane >> 4;
    const __half* U = g_uhat + (size_t)b * (NCAPS * 160);

    for (int r = 0; r < 3; r++) {
        float vreg[5];
        if (r > 0) {
#pragma unroll
            for (int m = 0; m < 5; m++) vreg[m] = vsm[m * 32 + lane];
        }
        float sp[5] = {0.f, 0.f, 0.f, 0.f, 0.f};

        for (int i = wid; i < NCAPS; i += 32) {
            float u[5];
            const __half* up = U + (size_t)i * 160;
#pragma unroll
            for (int m = 0; m < 5; m++) u[m] = __half2float(up[m * 32 + lane]);

            if (r == 0) {
#pragma unroll
                for (int m = 0; m < 5; m++) sp[m] += 0.1f * u[m];
                if ((lane & 15) == 0) {
#pragma unroll
                    for (int m = 0; m < 5; m++) bs[i * 10 + 2 * m + half] = 0.f;
                }
            } else {
                float bj[5];
#pragma unroll
                for (int m = 0; m < 5; m++) {
                    float t = u[m] * vreg[m];
                    t += __shfl_xor_sync(0xffffffff, t, 1);
                    t += __shfl_xor_sync(0xffffffff, t, 2);
                    t += __shfl_xor_sync(0xffffffff, t, 4);
                    t += __shfl_xor_sync(0xffffffff, t, 8);
                    bj[m] = bs[i * 10 + 2 * m + half] + t;
                }
                if (r == 1 && (lane & 15) == 0) {
#pragma unroll
                    for (int m = 0; m < 5; m++) bs[i * 10 + 2 * m + half] = bj[m];
                }
                float mx = bj[0];
#pragma unroll
                for (int m = 1; m < 5; m++) mx = fmaxf(mx, bj[m]);
                mx = fmaxf(mx, __shfl_xor_sync(0xffffffff, mx, 16));
                float es[5], ssum = 0.f;
#pragma unroll
                for (int m = 0; m < 5; m++) {
                    es[m] = expf(bj[m] - mx);
                    ssum += es[m];
                }
                ssum += __shfl_xor_sync(0xffffffff, ssum, 16);
                float inv = 1.f / ssum;
#pragma unroll
                for (int m = 0; m < 5; m++) sp[m] += (es[m] * inv) * u[m];
            }
        }
#pragma unroll
        for (int m = 0; m < 5; m++) swarp[wid * 160 + m * 32 + lane] = sp[m];
        __syncthreads();
        if (tid < 160) {
            float s = dc_bias[tid];
#pragma unroll
            for (int w = 0; w < 32; w++) s += swarp[w * 160 + tid];
            float sq = s * s;
#pragma unroll
            for (int o = 8; o > 0; o >>= 1)
                sq += __shfl_xor_sync(0xffffffff, sq, o);
            float scale = sq / ((1.f + sq) * sqrtf(sq));
            float v = s * scale;
            vsm[tid] = v;
            if (r == 2) out[b * 160 + tid] = v;
        }
        __syncthreads();
    }
}

// ---------------- launch ----------------
extern "C" void kernel_launch(void* const* d_in, const int* in_sizes, int n_in,
                              void* d_out, int out_size) {
    const float* x       = (const float*)d_in[0];
    const float* conv1_w = (const float*)d_in[1];
    const float* conv1_b = (const float*)d_in[2];
    const float* pc_w    = (const float*)d_in[3];
    const float* pc_b    = (const float*)d_in[4];
    const float* W       = (const float*)d_in[5];
    const float* dc_bias = (const float*)d_in[6];
    float* out = (float*)d_out;

    {
        dim3 grid(10, 256);
        conv1_kernel<<<grid, 256>>>(x, conv1_w, conv1_b);
    }
    {
        int total = MDIM * KDIM;
        convertA_kernel<<<(total + 255) / 256, 256>>>(pc_w);
    }
    {
        im2colB_kernel<<<NDIM / 8, 256>>>();   // 1152 blocks
    }
    {
        size_t smem = NSTAGE * STAGE_BYTES;  // 184320
        cudaFuncSetAttribute(gemm_mma_kernel,
                             cudaFuncAttributeMaxDynamicSharedMemorySize, (int)smem);
        dim3 grid(NDIM / 128, MDIM / 128);   // (72, 2) = 144 CTAs
        gemm_mma_kernel<<<grid, 256, smem>>>();
    }
    {
        int total = BATCH * NCAPS;
        squash_caps_kernel<<<(total + 255) / 256, 256>>>(pc_b);
    }
    {
        dim3 grid(NCAPS, 8);
        uhat_kernel<<<grid, 160>>>(W);
    }
    {
        size_t smem = (size_t)(11520 + 5120 + 160) * sizeof(float);  // 67200
        cudaFuncSetAttribute(routing_kernel,
                             cudaFuncAttributeMaxDynamicSharedMemorySize, (int)smem);
        routing_kernel<<<BATCH, 1024, smem>>>(dc_bias, out);
    }
}

// round 16
// speedup vs baseline: 1.0701x; 1.0701x over previous
#include <cuda_runtime.h>
#include <cuda_fp16.h>
#include <cstdint>
#include <cstddef>

// ---------------- problem constants ----------------
#define BATCH 256
#define C1 256
#define H1 20
#define KDIM 20736        // 256*81
#define NDIM 9216         // 256*36
#define MDIM 256
#define NPOS 36
#define NCAPS 1152
#define VIN 8
#define NOUT 10
#define VOUT 16

#define A_SCALE 64.0f
#define A_INV_SCALE (1.0f / 64.0f)

// ---------------- scratch (device globals; allocation-free) ----------------
__device__ __half g_h16[(size_t)BATCH * C1 * 400];             // conv1 out fp16
__device__ __half g_Ah[(size_t)MDIM * KDIM];                   // 64*weights fp16
__device__ __half g_Bh[(size_t)NDIM * KDIM];                   // im2col fp16
__device__ float g_c2[(size_t)MDIM * NDIM];                    // K-half 0 partial
__device__ float g_c2b[(size_t)MDIM * NDIM];                   // K-half 1 partial
__device__ float g_caps[(size_t)BATCH * NCAPS * VIN];
__device__ __half g_uhat[(size_t)BATCH * NCAPS * NOUT * VOUT]; // fp16 u_hat

// =================== PTX helpers ===================
__device__ __forceinline__ uint32_t smem_u32(const void* p) {
    uint32_t a;
    asm("{ .reg .u64 t; cvta.to.shared.u64 t, %1; cvt.u32.u64 %0, t; }"
        : "=r"(a) : "l"(p));
    return a;
}
__device__ __forceinline__ void cp_async16(uint32_t dst, const void* src) {
    asm volatile("cp.async.cg.shared.global [%0], [%1], 16;" :: "r"(dst), "l"(src));
}
#define CP_COMMIT() asm volatile("cp.async.commit_group;" ::: "memory")
#define CP_WAIT1()  asm volatile("cp.async.wait_group 1;" ::: "memory")

__device__ __forceinline__ void ldsm_x4(uint32_t* r, uint32_t addr) {
    asm volatile("ldmatrix.sync.aligned.m8n8.x4.shared.b16 {%0,%1,%2,%3}, [%4];"
                 : "=r"(r[0]), "=r"(r[1]), "=r"(r[2]), "=r"(r[3]) : "r"(addr));
}
__device__ __forceinline__ void mma_fp16(float* d, const uint32_t* a, const uint32_t* b) {
    asm volatile(
        "mma.sync.aligned.m16n8k16.row.col.f32.f16.f16.f32 "
        "{%0,%1,%2,%3}, {%4,%5,%6,%7}, {%8,%9}, {%0,%1,%2,%3};"
        : "+f"(d[0]), "+f"(d[1]), "+f"(d[2]), "+f"(d[3])
        : "r"(a[0]), "r"(a[1]), "r"(a[2]), "r"(a[3]), "r"(b[0]), "r"(b[1]));
}

// ---------------- conv1 (GEMM-style): [B,1,28,28] -> [B,256,20,20] fp16 out ------
__global__ __launch_bounds__(256) void conv1_kernel(const float* __restrict__ x,
                                                    const float* __restrict__ w,
                                                    const float* __restrict__ bias) {
    __shared__ float img[784];
    __shared__ float ws[81 * 128];
    int b = blockIdx.y;
    int oct = (blockIdx.x / 5) * 128;
    int pt = (blockIdx.x % 5) * 80;
    int tid = threadIdx.x;
    int tx = tid & 15, ty = tid >> 4;

    for (int i = tid; i < 784; i += 256) img[i] = x[(size_t)b * 784 + i];
    for (int idx = tid; idx < 81 * 128; idx += 256) {
        int o = idx / 81, k = idx - o * 81;
        ws[k * 128 + o] = w[(size_t)(oct + o) * 81 + k];
    }
    __syncthreads();

    int ibase[5];
#pragma unroll
    for (int q = 0; q < 5; q++) {
        int pos = pt + q * 16 + tx;
        int py = pos / 20, px = pos - py * 20;
        ibase[q] = py * 28 + px;
    }
    float acc[8][5];
#pragma unroll
    for (int o = 0; o < 8; o++) {
        float bv = bias[oct + ty * 8 + o];
#pragma unroll
        for (int q = 0; q < 5; q++) acc[o][q] = bv;
    }
#pragma unroll
    for (int r = 0; r < 9; r++) {
#pragma unroll
        for (int s = 0; s < 9; s++) {
            int k = r * 9 + s;
            int off = r * 28 + s;
            float iv[5];
#pragma unroll
            for (int q = 0; q < 5; q++) iv[q] = img[ibase[q] + off];
            float4 a0 = *(const float4*)&ws[k * 128 + ty * 8];
            float4 a1 = *(const float4*)&ws[k * 128 + ty * 8 + 4];
            float af[8] = {a0.x, a0.y, a0.z, a0.w, a1.x, a1.y, a1.z, a1.w};
#pragma unroll
            for (int o = 0; o < 8; o++)
#pragma unroll
                for (int q = 0; q < 5; q++) acc[o][q] += af[o] * iv[q];
        }
    }
#pragma unroll
    for (int o = 0; o < 8; o++) {
        int oc = oct + ty * 8 + o;
        __half* dst = g_h16 + ((size_t)b * C1 + oc) * 400 + pt + tx;
#pragma unroll
        for (int q = 0; q < 5; q++) dst[q * 16] = __float2half_rn(acc[o][q]);
    }
}

// ---------------- convert A: (64*pc_w) -> fp16 ----------------
__global__ void convertA_kernel(const float* __restrict__ pc_w) {
    int idx = blockIdx.x * blockDim.x + threadIdx.x;
    if (idx >= MDIM * KDIM) return;
    g_Ah[idx] = __float2half_rn(pc_w[idx] * A_SCALE);
}

// ---------------- im2col: warp-per-row, 16B stores, 1152 blocks x 256 ----------------
__global__ __launch_bounds__(256) void im2colB_kernel() {
    int n = blockIdx.x * 8 + (threadIdx.x >> 5);
    int lane = threadIdx.x & 31;
    int b = n / NPOS;
    int p = n - b * NPOS;
    int py = p / 6, px = p - py * 6;
    const __half* hb = g_h16 + (size_t)b * C1 * 400 + (2 * py) * H1 + 2 * px;
    __half* dst = g_Bh + (size_t)n * KDIM;

    for (int kg = 0; kg < 81; kg++) {
        int k0 = kg * 256 + lane * 8;
        __half h8[8];
#pragma unroll
        for (int e = 0; e < 8; e++) {
            int k = k0 + e;
            int ic = k / 81;
            int rs = k - ic * 81;
            int r = rs / 9, s = rs - r * 9;
            h8[e] = hb[ic * 400 + r * H1 + s];
        }
        *(uint4*)&dst[k0] = *(uint4*)h8;
    }
}

// ---------------- HMMA GEMM (split-K x2): C = A[256,K] * B[9216,K]^T ------------
// CTA 128x128, K-chunk 64, 3-stage cp.async, 8 warps (2m x 4n), warp tile 64x32.
// grid (72, 2, 2) = 288 CTAs -> 2 CTAs/SM. blockIdx.z selects K-half; partials
// go to g_c2 / g_c2b (summed in squash_caps).
#define GK 64
#define KHALF (KDIM / 2)              // 10368
#define KITERS (KHALF / GK)           // 162
#define PITCH 144
#define A_BYTES (128 * PITCH)         // 18432
#define B_BYTES (128 * PITCH)         // 18432
#define STAGE_BYTES (A_BYTES + B_BYTES)  // 36864
#define NSTAGE 3

__global__ __launch_bounds__(256, 2) void gemm_mma_kernel() {
    extern __shared__ char smem[];
    uint32_t sb = smem_u32(smem);
    int tid = threadIdx.x;
    int wid = tid >> 5, lane = tid & 31;
    int n0 = blockIdx.x * 128;
    int m0 = blockIdx.y * 128;
    int kz = blockIdx.z;
    int wm = wid >> 2;            // 0..1, m offset 64*wm
    int wn = wid & 3;             // 0..3, n offset 32*wn

    const __half* srcA = g_Ah + (size_t)m0 * KDIM + (size_t)kz * KHALF;
    const __half* srcB = g_Bh + (size_t)n0 * KDIM + (size_t)kz * KHALF;

#pragma unroll
    for (int st = 0; st < 2; st++) {
        int k0 = st * GK;
        uint32_t dstage = sb + st * STAGE_BYTES;
#pragma unroll
        for (int j = 0; j < 4; j++) {
            int q = tid + j * 256;
            int r = q >> 3, c = q & 7;
            cp_async16(dstage + r * PITCH + c * 16,
                       srcA + (size_t)r * KDIM + k0 + c * 8);
        }
#pragma unroll
        for (int j = 0; j < 4; j++) {
            int q = tid + j * 256;
            int r = q >> 3, c = q & 7;
            cp_async16(dstage + A_BYTES + r * PITCH + c * 16,
                       srcB + (size_t)r * KDIM + k0 + c * 8);
        }
        CP_COMMIT();
    }

    float acc[4][4][4];
#pragma unroll
    for (int i = 0; i < 4; i++)
#pragma unroll
        for (int j = 0; j < 4; j++)
#pragma unroll
            for (int v = 0; v < 4; v++) acc[i][j][v] = 0.f;

    int aRow = wm * 64 + (lane & 15);
    int aColB = (lane >> 4) * 16;
    int bGroup = lane >> 3;
    int bWithin = lane & 7;
    int bRowOff = wn * 32 + ((bGroup >> 1) << 3) + bWithin;
    int bColB = (bGroup & 1) * 16;

    for (int it = 0; it < KITERS; it++) {
        CP_WAIT1();
        __syncthreads();
        if (it + 2 < KITERS) {
            int k0 = (it + 2) * GK;
            uint32_t dstage = sb + ((it + 2) % NSTAGE) * STAGE_BYTES;
#pragma unroll
            for (int j = 0; j < 4; j++) {
                int q = tid + j * 256;
                int r = q >> 3, c = q & 7;
                cp_async16(dstage + r * PITCH + c * 16,
                           srcA + (size_t)r * KDIM + k0 + c * 8);
            }
#pragma unroll
            for (int j = 0; j < 4; j++) {
                int q = tid + j * 256;
                int r = q >> 3, c = q & 7;
                cp_async16(dstage + A_BYTES + r * PITCH + c * 16,
                           srcB + (size_t)r * KDIM + k0 + c * 8);
            }
        }
        CP_COMMIT();

        uint32_t stage = sb + (it % NSTAGE) * STAGE_BYTES;
#pragma unroll
        for (int ks = 0; ks < 4; ks++) {
            uint32_t kOffB = ks * 32;
            uint32_t aq[4][4], bq[4][2];
#pragma unroll
            for (int mf = 0; mf < 4; mf++) {
                uint32_t adr = stage + (aRow + mf * 16) * PITCH + aColB + kOffB;
                ldsm_x4(aq[mf], adr);
            }
#pragma unroll
            for (int jp = 0; jp < 2; jp++) {
                uint32_t tmp[4];
                uint32_t adr = stage + A_BYTES +
                               (bRowOff + jp * 16) * PITCH + bColB + kOffB;
                ldsm_x4(tmp, adr);
                bq[jp * 2 + 0][0] = tmp[0]; bq[jp * 2 + 0][1] = tmp[1];
                bq[jp * 2 + 1][0] = tmp[2]; bq[jp * 2 + 1][1] = tmp[3];
            }
#pragma unroll
            for (int mf = 0; mf < 4; mf++)
#pragma unroll
                for (int nf = 0; nf < 4; nf++)
                    mma_fp16(acc[mf][nf], aq[mf], bq[nf]);
        }
    }

    float* outbuf = kz ? g_c2b : g_c2;
    int g = lane >> 2, t = lane & 3;
#pragma unroll
    for (int mf = 0; mf < 4; mf++) {
#pragma unroll
        for (int nf = 0; nf < 4; nf++) {
            int m = m0 + wm * 64 + mf * 16 + g;
            int n = n0 + wn * 32 + nf * 8 + t * 2;
            float* p0 = outbuf + (size_t)m * NDIM + n;
            float* p1 = outbuf + (size_t)(m + 8) * NDIM + n;
            *(float2*)p0 = make_float2(acc[mf][nf][0], acc[mf][nf][1]);
            *(float2*)p1 = make_float2(acc[mf][nf][2], acc[mf][nf][3]);
        }
    }
}

// ---------------- bias + split-K sum + un-scale + squash -> caps[B,1152,8] -------
__global__ void squash_caps_kernel(const float* __restrict__ pcb) {
    int idx = blockIdx.x * blockDim.x + threadIdx.x;
    if (idx >= BATCH * NCAPS) return;
    int b = idx / NCAPS, i = idx % NCAPS;
    float v[8];
    float mag = 0.f;
#pragma unroll
    for (int k = 0; k < 8; k++) {
        int f = i * 8 + k;
        int oc = f / NPOS, p = f % NPOS;
        size_t off = (size_t)oc * NDIM + b * NPOS + p;
        float t = (g_c2[off] + g_c2b[off]) * A_INV_SCALE + pcb[oc];
        v[k] = t;
        mag += t * t;
    }
    float scale = mag / ((1.f + mag) * sqrtf(mag));
#pragma unroll
    for (int k = 0; k < 8; k++) g_caps[(size_t)idx * 8 + k] = v[k] * scale;
}

// ---------------- u_hat (fp16 out): grid (1152, 8), block 160 ----------------
__global__ void uhat_kernel(const float* __restrict__ W) {
    int i = blockIdx.x;
    int b0 = blockIdx.y * 32;
    __shared__ float Ws[160 * 8];
    int t = threadIdx.x;
    for (int q = t; q < 1280; q += 160) Ws[q] = W[(size_t)i * 1280 + q];
    __syncthreads();
    float wr[8];
#pragma unroll
    for (int k = 0; k < 8; k++) wr[k] = Ws[t * 8 + k];
    for (int b = b0; b < b0 + 32; b++) {
        const float* cp = g_caps + ((size_t)b * NCAPS + i) * 8;
        float acc = 0.f;
#pragma unroll
        for (int k = 0; k < 8; k++) acc += wr[k] * __ldg(cp + k);
        g_uhat[((size_t)b * NCAPS + i) * 160 + t] = __float2half_rn(acc);
    }
}

// ---------------- fused dynamic routing (u_hat fp16), 512 threads ----------------
__global__ __launch_bounds__(512) void routing_kernel(const float* __restrict__ dc_bias,
                                                      float* __restrict__ out) {
    extern __shared__ float sm[];
    float* bs = sm;                  // [1152*10]
    float* swarp = sm + 11520;       // [16*160]
    float* vsm = sm + 11520 + 2560;  // [160]

    int b = blockIdx.x;
    int tid = threadIdx.x;
    int wid = tid >> 5, lane = tid & 31;
    int half = lane >> 4;
    const __half* U = g_uhat + (size_t)b * (NCAPS * 160);

    for (int r = 0; r < 3; r++) {
        float vreg[5];
        if (r > 0) {
#pragma unroll
            for (int m = 0; m < 5; m++) vreg[m] = vsm[m * 32 + lane];
        }
        float sp[5] = {0.f, 0.f, 0.f, 0.f, 0.f};

        for (int i = wid; i < NCAPS; i += 16) {
            float u[5];
            const __half* up = U + (size_t)i * 160;
#pragma unroll
            for (int m = 0; m < 5; m++) u[m] = __half2float(up[m * 32 + lane]);

            if (r == 0) {
#pragma unroll
                for (int m = 0; m < 5; m++) sp[m] += 0.1f * u[m];
                if ((lane & 15) == 0) {
#pragma unroll
                    for (int m = 0; m < 5; m++) bs[i * 10 + 2 * m + half] = 0.f;
                }
            } else {
                float bj[5];
#pragma unroll
                for (int m = 0; m < 5; m++) {
                    float t = u[m] * vreg[m];
                    t += __shfl_xor_sync(0xffffffff, t, 1);
                    t += __shfl_xor_sync(0xffffffff, t, 2);
                    t += __shfl_xor_sync(0xffffffff, t, 4);
                    t += __shfl_xor_sync(0xffffffff, t, 8);
                    bj[m] = bs[i * 10 + 2 * m + half] + t;
                }
                if (r == 1 && (lane & 15) == 0) {
#pragma unroll
                    for (int m = 0; m < 5; m++) bs[i * 10 + 2 * m + half] = bj[m];
                }
                float mx = bj[0];
#pragma unroll
                for (int m = 1; m < 5; m++) mx = fmaxf(mx, bj[m]);
                mx = fmaxf(mx, __shfl_xor_sync(0xffffffff, mx, 16));
                float es[5], ssum = 0.f;
#pragma unroll
                for (int m = 0; m < 5; m++) {
                    es[m] = expf(bj[m] - mx);
                    ssum += es[m];
                }
                ssum += __shfl_xor_sync(0xffffffff, ssum, 16);
                float inv = 1.f / ssum;
#pragma unroll
                for (int m = 0; m < 5; m++) sp[m] += (es[m] * inv) * u[m];
            }
        }
#pragma unroll
        for (int m = 0; m < 5; m++) swarp[wid * 160 + m * 32 + lane] = sp[m];
        __syncthreads();
        if (tid < 160) {
            float s = dc_bias[tid];
#pragma unroll
            for (int w = 0; w < 16; w++) s += swarp[w * 160 + tid];
            float sq = s * s;
#pragma unroll
            for (int o = 8; o > 0; o >>= 1)
                sq += __shfl_xor_sync(0xffffffff, sq, o);
            float scale = sq / ((1.f + sq) * sqrtf(sq));
            float v = s * scale;
            vsm[tid] = v;
            if (r == 2) out[b * 160 + tid] = v;
        }
        __syncthreads();
    }
}

// ---------------- launch ----------------
extern "C" void kernel_launch(void* const* d_in, const int* in_sizes, int n_in,
                              void* d_out, int out_size) {
    const float* x       = (const float*)d_in[0];
    const float* conv1_w = (const float*)d_in[1];
    const float* conv1_b = (const float*)d_in[2];
    const float* pc_w    = (const float*)d_in[3];
    const float* pc_b    = (const float*)d_in[4];
    const float* W       = (const float*)d_in[5];
    const float* dc_bias = (const float*)d_in[6];
    float* out = (float*)d_out;

    {
        dim3 grid(10, 256);
        conv1_kernel<<<grid, 256>>>(x, conv1_w, conv1_b);
    }
    {
        int total = MDIM * KDIM;
        convertA_kernel<<<(total + 255) / 256, 256>>>(pc_w);
    }
    {
        im2colB_kernel<<<NDIM / 8, 256>>>();   // 1152 blocks
    }
    {
        size_t smem = NSTAGE * STAGE_BYTES;  // 110592
        cudaFuncSetAttribute(gemm_mma_kernel,
                             cudaFuncAttributeMaxDynamicSharedMemorySize, (int)smem);
        dim3 grid(NDIM / 128, MDIM / 128, 2);   // (72, 2, 2) = 288 CTAs
        gemm_mma_kernel<<<grid, 256, smem>>>();
    }
    {
        int total = BATCH * NCAPS;
        squash_caps_kernel<<<(total + 255) / 256, 256>>>(pc_b);
    }
    {
        dim3 grid(NCAPS, 8);
        uhat_kernel<<<grid, 160>>>(W);
    }
    {
        size_t smem = (size_t)(11520 + 2560 + 160) * sizeof(float);  // 56960
        cudaFuncSetAttribute(routing_kernel,
                             cudaFuncAttributeMaxDynamicSharedMemorySize, (int)smem);
        routing_kernel<<<BATCH, 512, smem>>>(dc_bias, out);
    }
}

// round 17
// speedup vs baseline: 1.1839x; 1.1064x over previous
#include <cuda_runtime.h>
#include <cuda_fp16.h>
#include <cstdint>
#include <cstddef>

// ---------------- problem constants ----------------
#define BATCH 256
#define C1 256
#define H1 20
#define KDIM 20736        // 256*81  (k' = rs*256 + ic ordering)
#define NDIM 9216         // 256*36
#define MDIM 256
#define NPOS 36
#define NCAPS 1152
#define VIN 8
#define NOUT 10
#define VOUT 16

#define A_SCALE 64.0f
#define A_INV_SCALE (1.0f / 64.0f)

// ---------------- scratch (device globals; allocation-free) ----------------
__device__ __half g_hT[(size_t)BATCH * 400 * C1];              // conv1 out [b][pos][ch]
__device__ __half g_Ah[(size_t)MDIM * KDIM];                   // 64*weights fp16, k'
__device__ __half g_Bh[(size_t)NDIM * KDIM];                   // im2col fp16, k'
__device__ float g_c2[(size_t)MDIM * NDIM];                    // K-half 0 partial
__device__ float g_c2b[(size_t)MDIM * NDIM];                   // K-half 1 partial
__device__ float g_caps[(size_t)BATCH * NCAPS * VIN];
__device__ __half g_uhat[(size_t)BATCH * NCAPS * NOUT * VOUT]; // fp16 u_hat

// =================== PTX helpers ===================
__device__ __forceinline__ uint32_t smem_u32(const void* p) {
    uint32_t a;
    asm("{ .reg .u64 t; cvta.to.shared.u64 t, %1; cvt.u32.u64 %0, t; }"
        : "=r"(a) : "l"(p));
    return a;
}
__device__ __forceinline__ void cp_async16(uint32_t dst, const void* src) {
    asm volatile("cp.async.cg.shared.global [%0], [%1], 16;" :: "r"(dst), "l"(src));
}
#define CP_COMMIT() asm volatile("cp.async.commit_group;" ::: "memory")
#define CP_WAIT1()  asm volatile("cp.async.wait_group 1;" ::: "memory")

__device__ __forceinline__ void ldsm_x4(uint32_t* r, uint32_t addr) {
    asm volatile("ldmatrix.sync.aligned.m8n8.x4.shared.b16 {%0,%1,%2,%3}, [%4];"
                 : "=r"(r[0]), "=r"(r[1]), "=r"(r[2]), "=r"(r[3]) : "r"(addr));
}
__device__ __forceinline__ void mma_fp16(float* d, const uint32_t* a, const uint32_t* b) {
    asm volatile(
        "mma.sync.aligned.m16n8k16.row.col.f32.f16.f16.f32 "
        "{%0,%1,%2,%3}, {%4,%5,%6,%7}, {%8,%9}, {%0,%1,%2,%3};"
        : "+f"(d[0]), "+f"(d[1]), "+f"(d[2]), "+f"(d[3])
        : "r"(a[0]), "r"(a[1]), "r"(a[2]), "r"(a[3]), "r"(b[0]), "r"(b[1]));
}

// ---------------- conv1: [B,1,28,28] -> g_hT[b][pos][oc] fp16 ----------------
__global__ __launch_bounds__(256) void conv1_kernel(const float* __restrict__ x,
                                                    const float* __restrict__ w,
                                                    const float* __restrict__ bias) {
    __shared__ float img[784];
    __shared__ float ws[81 * 128];
    int b = blockIdx.y;
    int oct = (blockIdx.x / 5) * 128;
    int pt = (blockIdx.x % 5) * 80;
    int tid = threadIdx.x;
    int tx = tid & 15, ty = tid >> 4;

    for (int i = tid; i < 784; i += 256) img[i] = x[(size_t)b * 784 + i];
    for (int idx = tid; idx < 81 * 128; idx += 256) {
        int o = idx / 81, k = idx - o * 81;
        ws[k * 128 + o] = w[(size_t)(oct + o) * 81 + k];
    }
    __syncthreads();

    int ibase[5];
#pragma unroll
    for (int q = 0; q < 5; q++) {
        int pos = pt + q * 16 + tx;
        int py = pos / 20, px = pos - py * 20;
        ibase[q] = py * 28 + px;
    }
    float acc[8][5];
#pragma unroll
    for (int o = 0; o < 8; o++) {
        float bv = bias[oct + ty * 8 + o];
#pragma unroll
        for (int q = 0; q < 5; q++) acc[o][q] = bv;
    }
#pragma unroll
    for (int r = 0; r < 9; r++) {
#pragma unroll
        for (int s = 0; s < 9; s++) {
            int k = r * 9 + s;
            int off = r * 28 + s;
            float iv[5];
#pragma unroll
            for (int q = 0; q < 5; q++) iv[q] = img[ibase[q] + off];
            float4 a0 = *(const float4*)&ws[k * 128 + ty * 8];
            float4 a1 = *(const float4*)&ws[k * 128 + ty * 8 + 4];
            float af[8] = {a0.x, a0.y, a0.z, a0.w, a1.x, a1.y, a1.z, a1.w};
#pragma unroll
            for (int o = 0; o < 8; o++)
#pragma unroll
                for (int q = 0; q < 5; q++) acc[o][q] += af[o] * iv[q];
        }
    }
    // store transposed: [b][pos][oc], 16B per (q)
#pragma unroll
    for (int q = 0; q < 5; q++) {
        int pos = pt + q * 16 + tx;
        __half h8[8];
#pragma unroll
        for (int o = 0; o < 8; o++) h8[o] = __float2half_rn(acc[o][q]);
        *(uint4*)&g_hT[((size_t)b * 400 + pos) * 256 + oct + ty * 8] = *(uint4*)h8;
    }
}

// ---------------- convert A: (64*pc_w) -> fp16 with k' = rs*256+ic ----------------
// grid 256 (m), 256 threads (ic). Stores coalesced; reads L1-local per thread.
__global__ __launch_bounds__(256) void convertA_kernel(const float* __restrict__ pc_w) {
    int m = blockIdx.x;
    int ic = threadIdx.x;
    const float* src = pc_w + (size_t)m * KDIM + (size_t)ic * 81;
    __half* dst = g_Ah + (size_t)m * KDIM + ic;
#pragma unroll 3
    for (int rs = 0; rs < 81; rs++)
        dst[(size_t)rs * 256] = __float2half_rn(src[rs] * A_SCALE);
}

// ---------------- im2col: streaming copy, warp-per-row n ----------------
// B[n][k'] with k' = rs*256+ic: contiguous 512B per (n, rs) from g_hT.
__global__ __launch_bounds__(256) void im2colB_kernel() {
    int n = blockIdx.x * 8 + (threadIdx.x >> 5);
    int lane = threadIdx.x & 31;
    int b = n / NPOS;
    int p = n - b * NPOS;
    int py = p / 6, px = p - py * 6;
    const __half* hb = g_hT + ((size_t)b * 400 + (2 * py) * H1 + 2 * px) * 256 + lane * 8;
    __half* dst = g_Bh + (size_t)n * KDIM + lane * 8;

#pragma unroll 3
    for (int rs = 0; rs < 81; rs++) {
        int r = rs / 9, s = rs - r * 9;
        uint4 v = *(const uint4*)(hb + (size_t)(r * H1 + s) * 256);
        *(uint4*)(dst + (size_t)rs * 256) = v;
    }
}

// ---------------- HMMA GEMM (split-K x2): C = A[256,K] * B[9216,K]^T ------------
// CTA 128x128, K-chunk 64, 3-stage cp.async, 8 warps (2m x 4n), warp tile 64x32.
// grid (72, 2, 2) = 288 CTAs -> 2 CTAs/SM.
#define GK 64
#define KHALF (KDIM / 2)              // 10368
#define KITERS (KHALF / GK)           // 162
#define PITCH 144
#define A_BYTES (128 * PITCH)         // 18432
#define B_BYTES (128 * PITCH)         // 18432
#define STAGE_BYTES (A_BYTES + B_BYTES)  // 36864
#define NSTAGE 3

__global__ __launch_bounds__(256, 2) void gemm_mma_kernel() {
    extern __shared__ char smem[];
    uint32_t sb = smem_u32(smem);
    int tid = threadIdx.x;
    int wid = tid >> 5, lane = tid & 31;
    int n0 = blockIdx.x * 128;
    int m0 = blockIdx.y * 128;
    int kz = blockIdx.z;
    int wm = wid >> 2;
    int wn = wid & 3;

    const __half* srcA = g_Ah + (size_t)m0 * KDIM + (size_t)kz * KHALF;
    const __half* srcB = g_Bh + (size_t)n0 * KDIM + (size_t)kz * KHALF;

#pragma unroll
    for (int st = 0; st < 2; st++) {
        int k0 = st * GK;
        uint32_t dstage = sb + st * STAGE_BYTES;
#pragma unroll
        for (int j = 0; j < 4; j++) {
            int q = tid + j * 256;
            int r = q >> 3, c = q & 7;
            cp_async16(dstage + r * PITCH + c * 16,
                       srcA + (size_t)r * KDIM + k0 + c * 8);
        }
#pragma unroll
        for (int j = 0; j < 4; j++) {
            int q = tid + j * 256;
            int r = q >> 3, c = q & 7;
            cp_async16(dstage + A_BYTES + r * PITCH + c * 16,
                       srcB + (size_t)r * KDIM + k0 + c * 8);
        }
        CP_COMMIT();
    }

    float acc[4][4][4];
#pragma unroll
    for (int i = 0; i < 4; i++)
#pragma unroll
        for (int j = 0; j < 4; j++)
#pragma unroll
            for (int v = 0; v < 4; v++) acc[i][j][v] = 0.f;

    int aRow = wm * 64 + (lane & 15);
    int aColB = (lane >> 4) * 16;
    int bGroup = lane >> 3;
    int bWithin = lane & 7;
    int bRowOff = wn * 32 + ((bGroup >> 1) << 3) + bWithin;
    int bColB = (bGroup & 1) * 16;

    for (int it = 0; it < KITERS; it++) {
        CP_WAIT1();
        __syncthreads();
        if (it + 2 < KITERS) {
            int k0 = (it + 2) * GK;
            uint32_t dstage = sb + ((it + 2) % NSTAGE) * STAGE_BYTES;
#pragma unroll
            for (int j = 0; j < 4; j++) {
                int q = tid + j * 256;
                int r = q >> 3, c = q & 7;
                cp_async16(dstage + r * PITCH + c * 16,
                           srcA + (size_t)r * KDIM + k0 + c * 8);
            }
#pragma unroll
            for (int j = 0; j < 4; j++) {
                int q = tid + j * 256;
                int r = q >> 3, c = q & 7;
                cp_async16(dstage + A_BYTES + r * PITCH + c * 16,
                           srcB + (size_t)r * KDIM + k0 + c * 8);
            }
        }
        CP_COMMIT();

        uint32_t stage = sb + (it % NSTAGE) * STAGE_BYTES;
#pragma unroll
        for (int ks = 0; ks < 4; ks++) {
            uint32_t kOffB = ks * 32;
            uint32_t aq[4][4], bq[4][2];
#pragma unroll
            for (int mf = 0; mf < 4; mf++) {
                uint32_t adr = stage + (aRow + mf * 16) * PITCH + aColB + kOffB;
                ldsm_x4(aq[mf], adr);
            }
#pragma unroll
            for (int jp = 0; jp < 2; jp++) {
                uint32_t tmp[4];
                uint32_t adr = stage + A_BYTES +
                               (bRowOff + jp * 16) * PITCH + bColB + kOffB;
                ldsm_x4(tmp, adr);
                bq[jp * 2 + 0][0] = tmp[0]; bq[jp * 2 + 0][1] = tmp[1];
                bq[jp * 2 + 1][0] = tmp[2]; bq[jp * 2 + 1][1] = tmp[3];
            }
#pragma unroll
            for (int mf = 0; mf < 4; mf++)
#pragma unroll
                for (int nf = 0; nf < 4; nf++)
                    mma_fp16(acc[mf][nf], aq[mf], bq[nf]);
        }
    }

    float* outbuf = kz ? g_c2b : g_c2;
    int g = lane >> 2, t = lane & 3;
#pragma unroll
    for (int mf = 0; mf < 4; mf++) {
#pragma unroll
        for (int nf = 0; nf < 4; nf++) {
            int m = m0 + wm * 64 + mf * 16 + g;
            int n = n0 + wn * 32 + nf * 8 + t * 2;
            float* p0 = outbuf + (size_t)m * NDIM + n;
            float* p1 = outbuf + (size_t)(m + 8) * NDIM + n;
            *(float2*)p0 = make_float2(acc[mf][nf][0], acc[mf][nf][1]);
            *(float2*)p1 = make_float2(acc[mf][nf][2], acc[mf][nf][3]);
        }
    }
}

// ---------------- bias + split-K sum + un-scale + squash -> caps[B,1152,8] -------
__global__ void squash_caps_kernel(const float* __restrict__ pcb) {
    int idx = blockIdx.x * blockDim.x + threadIdx.x;
    if (idx >= BATCH * NCAPS) return;
    int b = idx / NCAPS, i = idx % NCAPS;
    float v[8];
    float mag = 0.f;
#pragma unroll
    for (int k = 0; k < 8; k++) {
        int f = i * 8 + k;
        int oc = f / NPOS, p = f % NPOS;
        size_t off = (size_t)oc * NDIM + b * NPOS + p;
        float t = (g_c2[off] + g_c2b[off]) * A_INV_SCALE + pcb[oc];
        v[k] = t;
        mag += t * t;
    }
    float scale = mag / ((1.f + mag) * sqrtf(mag));
#pragma unroll
    for (int k = 0; k < 8; k++) g_caps[(size_t)idx * 8 + k] = v[k] * scale;
}

// ---------------- u_hat (fp16 out): grid (1152, 8), block 160 ----------------
__global__ void uhat_kernel(const float* __restrict__ W) {
    int i = blockIdx.x;
    int b0 = blockIdx.y * 32;
    __shared__ float Ws[160 * 8];
    int t = threadIdx.x;
    for (int q = t; q < 1280; q += 160) Ws[q] = W[(size_t)i * 1280 + q];
    __syncthreads();
    float wr[8];
#pragma unroll
    for (int k = 0; k < 8; k++) wr[k] = Ws[t * 8 + k];
    for (int b = b0; b < b0 + 32; b++) {
        const float* cp = g_caps + ((size_t)b * NCAPS + i) * 8;
        float acc = 0.f;
#pragma unroll
        for (int k = 0; k < 8; k++) acc += wr[k] * __ldg(cp + k);
        g_uhat[((size_t)b * NCAPS + i) * 160 + t] = __float2half_rn(acc);
    }
}

// ---------------- fused dynamic routing (u_hat fp16), 512 threads ----------------
__global__ __launch_bounds__(512) void routing_kernel(const float* __restrict__ dc_bias,
                                                      float* __restrict__ out) {
    extern __shared__ float sm[];
    float* bs = sm;                  // [1152*10]
    float* swarp = sm + 11520;       // [16*160]
    float* vsm = sm + 11520 + 2560;  // [160]

    int b = blockIdx.x;
    int tid = threadIdx.x;
    int wid = tid >> 5, lane = tid & 31;
    int half = lane >> 4;
    const __half* U = g_uhat + (size_t)b * (NCAPS * 160);

    for (int r = 0; r < 3; r++) {
        float vreg[5];
        if (r > 0) {
#pragma unroll
            for (int m = 0; m < 5; m++) vreg[m] = vsm[m * 32 + lane];
        }
        float sp[5] = {0.f, 0.f, 0.f, 0.f, 0.f};

        for (int i = wid; i < NCAPS; i += 16) {
            float u[5];
            const __half* up = U + (size_t)i * 160;
#pragma unroll
            for (int m = 0; m < 5; m++) u[m] = __half2float(up[m * 32 + lane]);

            if (r == 0) {
#pragma unroll
                for (int m = 0; m < 5; m++) sp[m] += 0.1f * u[m];
                if ((lane & 15) == 0) {
#pragma unroll
                    for (int m = 0; m < 5; m++) bs[i * 10 + 2 * m + half] = 0.f;
                }
            } else {
                float bj[5];
#pragma unroll
                for (int m = 0; m < 5; m++) {
                    float t = u[m] * vreg[m];
                    t += __shfl_xor_sync(0xffffffff, t, 1);
                    t += __shfl_xor_sync(0xffffffff, t, 2);
                    t += __shfl_xor_sync(0xffffffff, t, 4);
                    t += __shfl_xor_sync(0xffffffff, t, 8);
                    bj[m] = bs[i * 10 + 2 * m + half] + t;
                }
                if (r == 1 && (lane & 15) == 0) {
#pragma unroll
                    for (int m = 0; m < 5; m++) bs[i * 10 + 2 * m + half] = bj[m];
                }
                float mx = bj[0];
#pragma unroll
                for (int m = 1; m < 5; m++) mx = fmaxf(mx, bj[m]);
                mx = fmaxf(mx, __shfl_xor_sync(0xffffffff, mx, 16));
                float es[5], ssum = 0.f;
#pragma unroll
                for (int m = 0; m < 5; m++) {
                    es[m] = expf(bj[m] - mx);
                    ssum += es[m];
                }
                ssum += __shfl_xor_sync(0xffffffff, ssum, 16);
                float inv = 1.f / ssum;
#pragma unroll
                for (int m = 0; m < 5; m++) sp[m] += (es[m] * inv) * u[m];
            }
        }
#pragma unroll
        for (int m = 0; m < 5; m++) swarp[wid * 160 + m * 32 + lane] = sp[m];
        __syncthreads();
        if (tid < 160) {
            float s = dc_bias[tid];
#pragma unroll
            for (int w = 0; w < 16; w++) s += swarp[w * 160 + tid];
            float sq = s * s;
#pragma unroll
            for (int o = 8; o > 0; o >>= 1)
                sq += __shfl_xor_sync(0xffffffff, sq, o);
            float scale = sq / ((1.f + sq) * sqrtf(sq));
            float v = s * scale;
            vsm[tid] = v;
            if (r == 2) out[b * 160 + tid] = v;
        }
        __syncthreads();
    }
}

// ---------------- launch ----------------
extern "C" void kernel_launch(void* const* d_in, const int* in_sizes, int n_in,
                              void* d_out, int out_size) {
    const float* x       = (const float*)d_in[0];
    const float* conv1_w = (const float*)d_in[1];
    const float* conv1_b = (const float*)d_in[2];
    const float* pc_w    = (const float*)d_in[3];
    const float* pc_b    = (const float*)d_in[4];
    const float* W       = (const float*)d_in[5];
    const float* dc_bias = (const float*)d_in[6];
    float* out = (float*)d_out;

    {
        dim3 grid(10, 256);
        conv1_kernel<<<grid, 256>>>(x, conv1_w, conv1_b);
    }
    {
        convertA_kernel<<<MDIM, 256>>>(pc_w);
    }
    {
        im2colB_kernel<<<NDIM / 8, 256>>>();   // 1152 blocks
    }
    {
        size_t smem = NSTAGE * STAGE_BYTES;  // 110592
        cudaFuncSetAttribute(gemm_mma_kernel,
                             cudaFuncAttributeMaxDynamicSharedMemorySize, (int)smem);
        dim3 grid(NDIM / 128, MDIM / 128, 2);   // (72, 2, 2) = 288 CTAs
        gemm_mma_kernel<<<grid, 256, smem>>>();
    }
    {
        int total = BATCH * NCAPS;
        squash_caps_kernel<<<(total + 255) / 256, 256>>>(pc_b);
    }
    {
        dim3 grid(NCAPS, 8);
        uhat_kernel<<<grid, 160>>>(W);
    }
    {
        size_t smem = (size_t)(11520 + 2560 + 160) * sizeof(float);  // 56960
        cudaFuncSetAttribute(routing_kernel,
                             cudaFuncAttributeMaxDynamicSharedMemorySize, (int)smem);
        routing_kernel<<<BATCH, 512, smem>>>(dc_bias, out);
    }
}